// round 2
// baseline (speedup 1.0000x reference)
#include <cuda_runtime.h>
#include <math.h>

#define H 1024
#define S 2048
#define VOCAB 50257

// ---------------- scratch (__device__ globals) -----------------------------
__device__ float g_h0[H];
__device__ float g_h1[H];
__device__ float g_energ[S];
__device__ float g_ctx_part[32 * H];
__device__ float g_ctx[H];
__device__ float g_partA[VOCAB];
__device__ float g_partB[VOCAB];
__device__ float g_lse[1];

__device__ __forceinline__ float wred(float v) {
#pragma unroll
    for (int o = 16; o; o >>= 1) v += __shfl_xor_sync(0xffffffffu, v, o);
    return v;
}
__device__ __forceinline__ float sig_(float x) { return 1.0f / (1.0f + expf(-x)); }

// ---------------- fused GRU layer: one warp per output element j -----------
// Computes i_r,i_z,i_n (len NX4*4 input) and h_r,h_z,h_n (len H input),
// six independent FMA chains for deep MLP, then combines gates inline.
template <int NX4, bool GATHER>
__global__ void k_gru(const float* __restrict__ Wih, const float* __restrict__ Whh,
                      const float* __restrict__ bih, const float* __restrict__ bhh,
                      const float* __restrict__ xin,
                      const float* __restrict__ emb, const int* __restrict__ word,
                      const float* __restrict__ lastctx,
                      const float* __restrict__ hprev,
                      float* __restrict__ hout, float* __restrict__ hcopy) {
    int j = (blockIdx.x * blockDim.x + threadIdx.x) >> 5;
    int lane = threadIdx.x & 31;
    if (j >= H) return;
    const int n = NX4 * 4;
    const float4* wr4 = reinterpret_cast<const float4*>(Wih + (size_t)j * n);
    const float4* wz4 = reinterpret_cast<const float4*>(Wih + (size_t)(H + j) * n);
    const float4* wn4 = reinterpret_cast<const float4*>(Wih + (size_t)(2 * H + j) * n);
    const float4* ur4 = reinterpret_cast<const float4*>(Whh + (size_t)j * H);
    const float4* uz4 = reinterpret_cast<const float4*>(Whh + (size_t)(H + j) * H);
    const float4* un4 = reinterpret_cast<const float4*>(Whh + (size_t)(2 * H + j) * H);
    const float4* h4 = reinterpret_cast<const float4*>(hprev);

    float ir = 0.f, iz = 0.f, in_ = 0.f, hr = 0.f, hz = 0.f, hn = 0.f;

    if (GATHER) {
        const float4* e4 = reinterpret_cast<const float4*>(emb) + (size_t)word[0] * (H / 4);
        const float4* c4 = reinterpret_cast<const float4*>(lastctx);
#pragma unroll 2
        for (int i = lane; i < NX4; i += 32) {
            float4 xv = (i < H / 4) ? e4[i] : c4[i - H / 4];
            float4 a = wr4[i], b = wz4[i], c = wn4[i];
            ir  += a.x * xv.x + a.y * xv.y + a.z * xv.z + a.w * xv.w;
            iz  += b.x * xv.x + b.y * xv.y + b.z * xv.z + b.w * xv.w;
            in_ += c.x * xv.x + c.y * xv.y + c.z * xv.z + c.w * xv.w;
        }
    } else {
        const float4* x4 = reinterpret_cast<const float4*>(xin);
#pragma unroll 2
        for (int i = lane; i < NX4; i += 32) {
            float4 xv = x4[i];
            float4 a = wr4[i], b = wz4[i], c = wn4[i];
            ir  += a.x * xv.x + a.y * xv.y + a.z * xv.z + a.w * xv.w;
            iz  += b.x * xv.x + b.y * xv.y + b.z * xv.z + b.w * xv.w;
            in_ += c.x * xv.x + c.y * xv.y + c.z * xv.z + c.w * xv.w;
        }
    }
#pragma unroll 2
    for (int i = lane; i < H / 4; i += 32) {
        float4 hv = h4[i];
        float4 a = ur4[i], b = uz4[i], c = un4[i];
        hr += a.x * hv.x + a.y * hv.y + a.z * hv.z + a.w * hv.w;
        hz += b.x * hv.x + b.y * hv.y + b.z * hv.z + b.w * hv.w;
        hn += c.x * hv.x + c.y * hv.y + c.z * hv.z + c.w * hv.w;
    }
    ir = wred(ir); iz = wred(iz); in_ = wred(in_);
    hr = wred(hr); hz = wred(hz); hn = wred(hn);
    if (lane == 0) {
        float r = sig_((ir + bih[j]) + (hr + bhh[j]));
        float z = sig_((iz + bih[H + j]) + (hz + bhh[H + j]));
        float nn = tanhf((in_ + bih[2 * H + j]) + r * (hn + bhh[2 * H + j]));
        float h = (1.0f - z) * nn + z * hprev[j];
        hout[j] = h;
        hcopy[j] = h;
    }
}

// ---------------- generic warp-per-row matvec (energies) -------------------
__global__ void k_matvec(const float* __restrict__ W, const float* __restrict__ x,
                         float* __restrict__ y, int rows, int n4) {
    int r = (blockIdx.x * blockDim.x + threadIdx.x) >> 5;
    int lane = threadIdx.x & 31;
    if (r >= rows) return;
    const float4* w4 = reinterpret_cast<const float4*>(W) + (size_t)r * n4;
    const float4* x4 = reinterpret_cast<const float4*>(x);
    float s = 0.f;
#pragma unroll 4
    for (int i = lane; i < n4; i += 32) {
        float4 a = w4[i], c = x4[i];
        s += a.x * c.x + a.y * c.y + a.z * c.z + a.w * c.w;
    }
    s = wred(s);
    if (lane == 0) y[r] = s;
}

// ---------------- vocab half-GEMV: warp per row, 1024 columns --------------
__global__ void k_vocab(const float* __restrict__ W, const float* __restrict__ x,
                        float* __restrict__ part, int colOff) {
    int v = (blockIdx.x * blockDim.x + threadIdx.x) >> 5;
    int lane = threadIdx.x & 31;
    if (v >= VOCAB) return;
    const float4* w4 = reinterpret_cast<const float4*>(W + (size_t)v * 2048 + colOff);
    const float4* x4 = reinterpret_cast<const float4*>(x);
    float s = 0.f;
#pragma unroll 8
    for (int i = lane; i < 256; i += 32) {
        float4 a = w4[i], c = x4[i];
        s += a.x * c.x + a.y * c.y + a.z * c.z + a.w * c.w;
    }
    s = wred(s);
    if (lane == 0) part[v] = s;
}

// ---------------- attention softmax (S=2048, one block) --------------------
__global__ void k_attn_softmax(float* __restrict__ wout) {
    __shared__ float red[1024];
    int t = threadIdx.x;
    float a = g_energ[t], b = g_energ[t + 1024];
    red[t] = fmaxf(a, b);
    __syncthreads();
    for (int s = 512; s > 0; s >>= 1) {
        if (t < s) red[t] = fmaxf(red[t], red[t + s]);
        __syncthreads();
    }
    float m = red[0];
    __syncthreads();
    float ea = expf(a - m), eb = expf(b - m);
    red[t] = ea + eb;
    __syncthreads();
    for (int s = 512; s > 0; s >>= 1) {
        if (t < s) red[t] += red[t + s];
        __syncthreads();
    }
    float inv = 1.0f / red[0];
    wout[t] = ea * inv;
    wout[t + 1024] = eb * inv;
}

// ---------------- context: deterministic two-stage reduction ---------------
__global__ void k_ctx_partial(const float* __restrict__ enc, const float* __restrict__ w) {
    int d = threadIdx.x;
    int s0 = blockIdx.x * 64;
    float acc = 0.f;
#pragma unroll 8
    for (int s = s0; s < s0 + 64; ++s)
        acc += w[s] * enc[(size_t)s * H + d];
    g_ctx_part[blockIdx.x * H + d] = acc;
}

__global__ void k_ctx_reduce(float* __restrict__ ctx_out) {
    int d = blockIdx.x * blockDim.x + threadIdx.x;
    if (d >= H) return;
    float acc = 0.f;
#pragma unroll
    for (int c = 0; c < 32; ++c) acc += g_ctx_part[c * H + d];
    g_ctx[d] = acc;
    ctx_out[d] = acc;
}

// ---------------- logsumexp over combined logits (L2-hot) ------------------
__global__ void k_lse(const float* __restrict__ bout) {
    __shared__ float red[1024];
    int t = threadIdx.x;
    float m = -INFINITY;
    for (int v = t; v < VOCAB; v += 1024)
        m = fmaxf(m, g_partA[v] + g_partB[v] + bout[v]);
    red[t] = m;
    __syncthreads();
    for (int s = 512; s > 0; s >>= 1) {
        if (t < s) red[t] = fmaxf(red[t], red[t + s]);
        __syncthreads();
    }
    m = red[0];
    __syncthreads();
    float sum = 0.f;
    for (int v = t; v < VOCAB; v += 1024)
        sum += expf(g_partA[v] + g_partB[v] + bout[v] - m);
    red[t] = sum;
    __syncthreads();
    for (int s = 512; s > 0; s >>= 1) {
        if (t < s) red[t] += red[t + s];
        __syncthreads();
    }
    if (t == 0) g_lse[0] = m + logf(red[0]);
}

__global__ void k_finalize(float* __restrict__ outlog, const float* __restrict__ bout) {
    int v = blockIdx.x * blockDim.x + threadIdx.x;
    if (v < VOCAB) outlog[v] = g_partA[v] + g_partB[v] + bout[v] - g_lse[0];
}

// ---------------- launch ---------------------------------------------------

extern "C" void kernel_launch(void* const* d_in, const int* in_sizes, int n_in,
                              void* d_out, int out_size) {
    const int*   word     = (const int*)  d_in[0];
    const float* last_ctx = (const float*)d_in[1];
    const float* last_hid = (const float*)d_in[2];   // (2,1,H)
    const float* enc      = (const float*)d_in[3];   // (S,1,H)
    const float* emb      = (const float*)d_in[4];
    const float* W_ih0    = (const float*)d_in[5];
    const float* W_hh0    = (const float*)d_in[6];
    const float* b_ih0    = (const float*)d_in[7];
    const float* b_hh0    = (const float*)d_in[8];
    const float* W_ih1    = (const float*)d_in[9];
    const float* W_hh1    = (const float*)d_in[10];
    const float* b_ih1    = (const float*)d_in[11];
    const float* b_hh1    = (const float*)d_in[12];
    const float* W_out    = (const float*)d_in[13];
    const float* b_out    = (const float*)d_in[14];

    float* out       = (float*)d_out;
    float* out_logit = out;                  // [0, V)
    float* out_ctx   = out + VOCAB;          // [V, V+H)
    float* out_h0    = out + VOCAB + H;      // hidden[0]
    float* out_h1    = out + VOCAB + 2 * H;  // hidden[1]
    float* out_attn  = out + VOCAB + 3 * H;  // [.., ..+S)

    float *ph0, *ph1, *peng, *pctx, *pA, *pB;
    cudaGetSymbolAddress((void**)&ph0,  g_h0);
    cudaGetSymbolAddress((void**)&ph1,  g_h1);
    cudaGetSymbolAddress((void**)&peng, g_energ);
    cudaGetSymbolAddress((void**)&pctx, g_ctx);
    cudaGetSymbolAddress((void**)&pA,   g_partA);
    cudaGetSymbolAddress((void**)&pB,   g_partB);

    // lazy one-time resources (created on the uncaptured correctness call)
    static cudaStream_t s1 = nullptr;
    static cudaEvent_t evFork = nullptr, evJoin = nullptr;
    if (!s1) {
        cudaStreamCreateWithFlags(&s1, cudaStreamNonBlocking);
        cudaEventCreateWithFlags(&evFork, cudaEventDisableTiming);
        cudaEventCreateWithFlags(&evJoin, cudaEventDisableTiming);
    }

    const int VBLK = (VOCAB * 32 + 255) / 256;

    // 1) GRU layer 0 (fused, gather x = [emb[word], last_context] inline)
    k_gru<512, true><<<128, 256>>>(W_ih0, W_hh0, b_ih0, b_hh0, nullptr,
                                   emb, word, last_ctx, last_hid, ph0, out_h0);
    // 2) GRU layer 1 (fused)
    k_gru<256, false><<<128, 256>>>(W_ih1, W_hh1, b_ih1, b_hh1, ph0,
                                    nullptr, nullptr, nullptr, last_hid + H, ph1, out_h1);

    // 3) fork: vocab half-A (W_out[:, :1024] @ h1) overlaps the attention chain
    cudaEventRecord(evFork, 0);
    cudaStreamWaitEvent(s1, evFork, 0);
    k_vocab<<<VBLK, 256, 0, s1>>>(W_out, ph1, pA, 0);
    cudaEventRecord(evJoin, s1);

    // 4) attention chain on main stream
    k_matvec<<<(S * 32 + 255) / 256, 256>>>(enc, ph1, peng, S, 256);
    k_attn_softmax<<<1, 1024>>>(out_attn);
    k_ctx_partial<<<32, 1024>>>(enc, out_attn);
    k_ctx_reduce<<<4, 256>>>(out_ctx);

    // 5) vocab half-B (W_out[:, 1024:] @ context)
    k_vocab<<<VBLK, 256>>>(W_out, pctx, pB, 1024);

    // 6) join, then log_softmax epilogue (L2-hot passes over part sums)
    cudaStreamWaitEvent(0, evJoin, 0);
    k_lse<<<1, 1024>>>(b_out);
    k_finalize<<<(VOCAB + 255) / 256, 256>>>(out_logit, b_out);
}

// round 4
// speedup vs baseline: 1.1910x; 1.1910x over previous
#include <cuda_runtime.h>
#include <math.h>

#define H 1024
#define S 2048
#define VOCAB 50257

// ---------------- scratch (__device__ globals) -----------------------------
__device__ float g_h0[H];
__device__ float g_h1[H];
__device__ float g_energ[S];
__device__ float g_am[256];         // per-block energy max
__device__ float g_as[256];         // per-block expsum
__device__ float g_attn_lse[1];
__device__ float g_ctx_part[32 * H];
__device__ float g_ctx[H];
__device__ float g_xout[2 * H];     // [h1, ctx]
__device__ float g_lm[64];          // logit lse partials
__device__ float g_ls[64];
__device__ float g_lse[1];

__device__ __forceinline__ float wred(float v) {
#pragma unroll
    for (int o = 16; o; o >>= 1) v += __shfl_xor_sync(0xffffffffu, v, o);
    return v;
}
__device__ __forceinline__ float sig_(float x) { return 1.0f / (1.0f + expf(-x)); }

// online (max, expsum) merge — deterministic, guards empty partials
__device__ __forceinline__ void msmerge(float& m1, float& s1, float m2, float s2) {
    if (s2 == 0.0f) return;
    if (s1 == 0.0f) { m1 = m2; s1 = s2; return; }
    if (m2 > m1) { float tm = m1; m1 = m2; m2 = tm; float ts = s1; s1 = s2; s2 = ts; }
    s1 += s2 * expf(m2 - m1);
}

// ---------------- fused GRU layer: one BLOCK (256 thr) per output j --------
template <int N, bool GATHER>
__global__ void k_gru(const float* __restrict__ Wih, const float* __restrict__ Whh,
                      const float* __restrict__ bih, const float* __restrict__ bhh,
                      const float* __restrict__ xin,
                      const float* __restrict__ emb, const int* __restrict__ word,
                      const float* __restrict__ lastctx,
                      const float* __restrict__ hprev,
                      float* __restrict__ hout, float* __restrict__ hcopy) {
    __shared__ float smem[6][8];
    int j = blockIdx.x;
    int tid = threadIdx.x;
    int lane = tid & 31, warp = tid >> 5;

    const float4* wr4 = reinterpret_cast<const float4*>(Wih + (size_t)j * N);
    const float4* wz4 = reinterpret_cast<const float4*>(Wih + (size_t)(H + j) * N);
    const float4* wn4 = reinterpret_cast<const float4*>(Wih + (size_t)(2 * H + j) * N);
    const float4* ur4 = reinterpret_cast<const float4*>(Whh + (size_t)j * H);
    const float4* uz4 = reinterpret_cast<const float4*>(Whh + (size_t)(H + j) * H);
    const float4* un4 = reinterpret_cast<const float4*>(Whh + (size_t)(2 * H + j) * H);
    const float4* h4  = reinterpret_cast<const float4*>(hprev);

    float ir = 0.f, iz = 0.f, in_ = 0.f, hr = 0.f, hz = 0.f, hn = 0.f;

    if (GATHER) {
        const float4* e4 = reinterpret_cast<const float4*>(emb) + (size_t)word[0] * (H / 4);
        const float4* c4 = reinterpret_cast<const float4*>(lastctx);
#pragma unroll
        for (int i = tid; i < N / 4; i += 256) {
            float4 xv = (i < H / 4) ? e4[i] : c4[i - H / 4];
            float4 a = wr4[i], b = wz4[i], c = wn4[i];
            ir  += a.x * xv.x + a.y * xv.y + a.z * xv.z + a.w * xv.w;
            iz  += b.x * xv.x + b.y * xv.y + b.z * xv.z + b.w * xv.w;
            in_ += c.x * xv.x + c.y * xv.y + c.z * xv.z + c.w * xv.w;
        }
    } else {
        const float4* x4 = reinterpret_cast<const float4*>(xin);
#pragma unroll
        for (int i = tid; i < N / 4; i += 256) {
            float4 xv = x4[i];
            float4 a = wr4[i], b = wz4[i], c = wn4[i];
            ir  += a.x * xv.x + a.y * xv.y + a.z * xv.z + a.w * xv.w;
            iz  += b.x * xv.x + b.y * xv.y + b.z * xv.z + b.w * xv.w;
            in_ += c.x * xv.x + c.y * xv.y + c.z * xv.z + c.w * xv.w;
        }
    }
    {   // H/4 = 256 float4 -> exactly one iteration per thread
        float4 hv = h4[tid];
        float4 a = ur4[tid], b = uz4[tid], c = un4[tid];
        hr = a.x * hv.x + a.y * hv.y + a.z * hv.z + a.w * hv.w;
        hz = b.x * hv.x + b.y * hv.y + b.z * hv.z + b.w * hv.w;
        hn = c.x * hv.x + c.y * hv.y + c.z * hv.z + c.w * hv.w;
    }
    ir = wred(ir); iz = wred(iz); in_ = wred(in_);
    hr = wred(hr); hz = wred(hz); hn = wred(hn);
    if (lane == 0) {
        smem[0][warp] = ir; smem[1][warp] = iz; smem[2][warp] = in_;
        smem[3][warp] = hr; smem[4][warp] = hz; smem[5][warp] = hn;
    }
    __syncthreads();
    if (tid == 0) {
        float v[6];
#pragma unroll
        for (int g = 0; g < 6; ++g) {
            float s = smem[g][0];
#pragma unroll
            for (int w = 1; w < 8; ++w) s += smem[g][w];
            v[g] = s;
        }
        float r  = sig_((v[0] + bih[j]) + (v[3] + bhh[j]));
        float z  = sig_((v[1] + bih[H + j]) + (v[4] + bhh[H + j]));
        float nn = tanhf((v[2] + bih[2 * H + j]) + r * (v[5] + bhh[2 * H + j]));
        float h  = (1.0f - z) * nn + z * hprev[j];
        hout[j] = h;
        hcopy[j] = h;
    }
}

// ---------------- energies + per-block softmax partials --------------------
// 256 blocks x 256 threads; warp per s-row (8 rows/block)
__global__ void k_energy(const float* __restrict__ enc, const float* __restrict__ h1) {
    __shared__ float se[8];
    int lane = threadIdx.x & 31, warp = threadIdx.x >> 5;
    int s = blockIdx.x * 8 + warp;
    const float4* w4 = reinterpret_cast<const float4*>(enc) + (size_t)s * 256;
    const float4* x4 = reinterpret_cast<const float4*>(h1);
    float e = 0.f;
#pragma unroll
    for (int i = lane; i < 256; i += 32) {
        float4 a = w4[i], c = x4[i];
        e += a.x * c.x + a.y * c.y + a.z * c.z + a.w * c.w;
    }
    e = wred(e);
    if (lane == 0) { g_energ[s] = e; se[warp] = e; }
    __syncthreads();
    if (threadIdx.x == 0) {
        float m = se[0];
#pragma unroll
        for (int w = 1; w < 8; ++w) m = fmaxf(m, se[w]);
        float sum = 0.f;
#pragma unroll
        for (int w = 0; w < 8; ++w) sum += expf(se[w] - m);
        g_am[blockIdx.x] = m;
        g_as[blockIdx.x] = sum;
    }
}

// 1 warp: combine 256 (m,s) partials -> attention logsumexp
__global__ void k_attn_lse() {
    int lane = threadIdx.x;
    float m = -INFINITY, s = 0.f;
#pragma unroll
    for (int i = 0; i < 8; ++i)
        msmerge(m, s, g_am[lane + 32 * i], g_as[lane + 32 * i]);
#pragma unroll
    for (int o = 16; o; o >>= 1) {
        float m2 = __shfl_xor_sync(0xffffffffu, m, o);
        float s2 = __shfl_xor_sync(0xffffffffu, s, o);
        msmerge(m, s, m2, s2);
    }
    if (lane == 0) g_attn_lse[0] = m + logf(s);
}

// context partial: 32 blocks x 1024 threads; also writes normalized attn out
__global__ void k_ctx(const float* __restrict__ enc, float* __restrict__ attn_out) {
    int d = threadIdx.x;
    int s0 = blockIdx.x * 64;
    float lse = g_attn_lse[0];
    if (d < 64) attn_out[s0 + d] = expf(g_energ[s0 + d] - lse);
    float acc = 0.f;
#pragma unroll 8
    for (int s = s0; s < s0 + 64; ++s)
        acc += expf(g_energ[s] - lse) * enc[(size_t)s * H + d];
    g_ctx_part[blockIdx.x * H + d] = acc;
}

// reduce 32 partials -> ctx; assemble xout = [h1, ctx]
__global__ void k_ctx_reduce(float* __restrict__ ctx_out) {
    int d = blockIdx.x * blockDim.x + threadIdx.x;
    float acc = 0.f;
#pragma unroll
    for (int c = 0; c < 32; ++c) acc += g_ctx_part[c * H + d];
    g_ctx[d] = acc;
    ctx_out[d] = acc;
    g_xout[d] = g_h1[d];
    g_xout[H + d] = acc;
}

// vocab GEMV: warp per row, full 2048 cols, bias fused
__global__ void k_vocab(const float* __restrict__ W, const float* __restrict__ b,
                        float* __restrict__ logits) {
    int v = (blockIdx.x * blockDim.x + threadIdx.x) >> 5;
    int lane = threadIdx.x & 31;
    if (v >= VOCAB) return;
    const float4* w4 = reinterpret_cast<const float4*>(W) + (size_t)v * 512;
    const float4* x4 = reinterpret_cast<const float4*>(g_xout);
    float s = 0.f;
#pragma unroll 8
    for (int i = lane; i < 512; i += 32) {
        float4 a = w4[i], c = x4[i];
        s += a.x * c.x + a.y * c.y + a.z * c.z + a.w * c.w;
    }
    s = wred(s);
    if (lane == 0) logits[v] = s + b[v];
}

// logit lse stage 1: 64 blocks x 256 threads, online (m,s) per block
__global__ void k_lse1(const float* __restrict__ logits) {
    __shared__ float sm[8], ss[8];
    const int CH = 786;
    int b = blockIdx.x;
    int lo = b * CH;
    int hi = min(lo + CH, VOCAB);
    int lane = threadIdx.x & 31, warp = threadIdx.x >> 5;
    float m = -INFINITY, s = 0.f;
    for (int v = lo + threadIdx.x; v < hi; v += 256) {
        float x = logits[v];
        if (x > m) { s = s * expf(m - x) + 1.0f; m = x; }
        else s += expf(x - m);
    }
#pragma unroll
    for (int o = 16; o; o >>= 1) {
        float m2 = __shfl_xor_sync(0xffffffffu, m, o);
        float s2 = __shfl_xor_sync(0xffffffffu, s, o);
        msmerge(m, s, m2, s2);
    }
    if (lane == 0) { sm[warp] = m; ss[warp] = s; }
    __syncthreads();
    if (threadIdx.x == 0) {
        float M = sm[0], Ssum = ss[0];
#pragma unroll
        for (int w = 1; w < 8; ++w) msmerge(M, Ssum, sm[w], ss[w]);
        g_lm[b] = M; g_ls[b] = Ssum;
    }
}

// logit lse stage 2: 1 warp combines 64 partials
__global__ void k_lse2() {
    int lane = threadIdx.x;
    float m = g_lm[lane], s = g_ls[lane];
    msmerge(m, s, g_lm[lane + 32], g_ls[lane + 32]);
#pragma unroll
    for (int o = 16; o; o >>= 1) {
        float m2 = __shfl_xor_sync(0xffffffffu, m, o);
        float s2 = __shfl_xor_sync(0xffffffffu, s, o);
        msmerge(m, s, m2, s2);
    }
    if (lane == 0) g_lse[0] = m + logf(s);
}

__global__ void k_finalize(float* __restrict__ logits) {
    int v = blockIdx.x * blockDim.x + threadIdx.x;
    if (v < VOCAB) logits[v] -= g_lse[0];
}

// ---------------- launch ---------------------------------------------------

extern "C" void kernel_launch(void* const* d_in, const int* in_sizes, int n_in,
                              void* d_out, int out_size) {
    const int*   word     = (const int*)  d_in[0];
    const float* last_ctx = (const float*)d_in[1];
    const float* last_hid = (const float*)d_in[2];   // (2,1,H)
    const float* enc      = (const float*)d_in[3];   // (S,1,H)
    const float* emb      = (const float*)d_in[4];
    const float* W_ih0    = (const float*)d_in[5];
    const float* W_hh0    = (const float*)d_in[6];
    const float* b_ih0    = (const float*)d_in[7];
    const float* b_hh0    = (const float*)d_in[8];
    const float* W_ih1    = (const float*)d_in[9];
    const float* W_hh1    = (const float*)d_in[10];
    const float* b_ih1    = (const float*)d_in[11];
    const float* b_hh1    = (const float*)d_in[12];
    const float* W_out    = (const float*)d_in[13];
    const float* b_out    = (const float*)d_in[14];

    float* out       = (float*)d_out;
    float* out_logit = out;                  // [0, V)
    float* out_ctx   = out + VOCAB;          // context
    float* out_h0    = out + VOCAB + H;      // hidden[0]
    float* out_h1    = out + VOCAB + 2 * H;  // hidden[1]
    float* out_attn  = out + VOCAB + 3 * H;  // attn weights

    float *ph0, *ph1;
    cudaGetSymbolAddress((void**)&ph0, g_h0);
    cudaGetSymbolAddress((void**)&ph1, g_h1);

    // 1-2) fused GRU layers, block-per-output-element
    k_gru<2048, true><<<H, 256>>>(W_ih0, W_hh0, b_ih0, b_hh0, nullptr,
                                  emb, word, last_ctx, last_hid, ph0, out_h0);
    k_gru<1024, false><<<H, 256>>>(W_ih1, W_hh1, b_ih1, b_hh1, ph0,
                                   nullptr, nullptr, nullptr, last_hid + H, ph1, out_h1);

    // 3-6) attention
    k_energy<<<256, 256>>>(enc, ph1);
    k_attn_lse<<<1, 32>>>();
    k_ctx<<<32, 1024>>>(enc, out_attn);
    k_ctx_reduce<<<4, 256>>>(out_ctx);

    // 7) vocab logits (bias fused)
    k_vocab<<<(VOCAB * 32 + 255) / 256, 256>>>(W_out, b_out, out_logit);

    // 8-10) log_softmax
    k_lse1<<<64, 256>>>(out_logit);
    k_lse2<<<1, 32>>>();
    k_finalize<<<(VOCAB + 255) / 256, 256>>>(out_logit);
}

// round 5
// speedup vs baseline: 1.2183x; 1.0229x over previous
#include <cuda_runtime.h>
#include <math.h>

#define H 1024
#define S 2048
#define VOCAB 50257

// ---------------- scratch (__device__ globals) -----------------------------
__device__ float g_h0[H];
__device__ float g_h1[H];
__device__ float g_energ[S];
__device__ float g_am[64];          // per-block energy (max, expsum) partials
__device__ float g_as[64];
__device__ float g_ctx_part[32 * H];
__device__ float g_ctx[H];
__device__ float g_xout[2 * H];     // [h1, ctx]
__device__ float g_lm[64];          // logit lse partials
__device__ float g_ls[64];

__device__ __forceinline__ float wred(float v) {
#pragma unroll
    for (int o = 16; o; o >>= 1) v += __shfl_xor_sync(0xffffffffu, v, o);
    return v;
}
__device__ __forceinline__ float sig_(float x) { return 1.0f / (1.0f + expf(-x)); }

// online (max, expsum) merge — deterministic, guards empty partials
__device__ __forceinline__ void msmerge(float& m1, float& s1, float m2, float s2) {
    if (s2 == 0.0f) return;
    if (s1 == 0.0f) { m1 = m2; s1 = s2; return; }
    if (m2 > m1) { float tm = m1; m1 = m2; m2 = tm; float ts = s1; s1 = s2; s2 = ts; }
    s1 += s2 * expf(m2 - m1);
}

// ---------------- fused GRU layer: one BLOCK (256 thr) per output j --------
template <int N, bool GATHER>
__global__ void k_gru(const float* __restrict__ Wih, const float* __restrict__ Whh,
                      const float* __restrict__ bih, const float* __restrict__ bhh,
                      const float* __restrict__ xin,
                      const float* __restrict__ emb, const int* __restrict__ word,
                      const float* __restrict__ lastctx,
                      const float* __restrict__ hprev,
                      float* __restrict__ hout, float* __restrict__ hcopy) {
    __shared__ float smem[6][8];
    int j = blockIdx.x;
    int tid = threadIdx.x;
    int lane = tid & 31, warp = tid >> 5;

    const float4* wr4 = reinterpret_cast<const float4*>(Wih + (size_t)j * N);
    const float4* wz4 = reinterpret_cast<const float4*>(Wih + (size_t)(H + j) * N);
    const float4* wn4 = reinterpret_cast<const float4*>(Wih + (size_t)(2 * H + j) * N);
    const float4* ur4 = reinterpret_cast<const float4*>(Whh + (size_t)j * H);
    const float4* uz4 = reinterpret_cast<const float4*>(Whh + (size_t)(H + j) * H);
    const float4* un4 = reinterpret_cast<const float4*>(Whh + (size_t)(2 * H + j) * H);
    const float4* h4  = reinterpret_cast<const float4*>(hprev);

    float ir = 0.f, iz = 0.f, in_ = 0.f, hr = 0.f, hz = 0.f, hn = 0.f;

    if (GATHER) {
        const float4* e4 = reinterpret_cast<const float4*>(emb) + (size_t)word[0] * (H / 4);
        const float4* c4 = reinterpret_cast<const float4*>(lastctx);
#pragma unroll
        for (int i = tid; i < N / 4; i += 256) {
            float4 xv = (i < H / 4) ? e4[i] : c4[i - H / 4];
            float4 a = wr4[i], b = wz4[i], c = wn4[i];
            ir  += a.x * xv.x + a.y * xv.y + a.z * xv.z + a.w * xv.w;
            iz  += b.x * xv.x + b.y * xv.y + b.z * xv.z + b.w * xv.w;
            in_ += c.x * xv.x + c.y * xv.y + c.z * xv.z + c.w * xv.w;
        }
    } else {
        const float4* x4 = reinterpret_cast<const float4*>(xin);
#pragma unroll
        for (int i = tid; i < N / 4; i += 256) {
            float4 xv = x4[i];
            float4 a = wr4[i], b = wz4[i], c = wn4[i];
            ir  += a.x * xv.x + a.y * xv.y + a.z * xv.z + a.w * xv.w;
            iz  += b.x * xv.x + b.y * xv.y + b.z * xv.z + b.w * xv.w;
            in_ += c.x * xv.x + c.y * xv.y + c.z * xv.z + c.w * xv.w;
        }
    }
    {   // H/4 = 256 float4 -> exactly one iteration per thread
        float4 hv = h4[tid];
        float4 a = ur4[tid], b = uz4[tid], c = un4[tid];
        hr = a.x * hv.x + a.y * hv.y + a.z * hv.z + a.w * hv.w;
        hz = b.x * hv.x + b.y * hv.y + b.z * hv.z + b.w * hv.w;
        hn = c.x * hv.x + c.y * hv.y + c.z * hv.z + c.w * hv.w;
    }
    ir = wred(ir); iz = wred(iz); in_ = wred(in_);
    hr = wred(hr); hz = wred(hz); hn = wred(hn);
    if (lane == 0) {
        smem[0][warp] = ir; smem[1][warp] = iz; smem[2][warp] = in_;
        smem[3][warp] = hr; smem[4][warp] = hz; smem[5][warp] = hn;
    }
    __syncthreads();
    if (tid == 0) {
        float v[6];
#pragma unroll
        for (int g = 0; g < 6; ++g) {
            float s = smem[g][0];
#pragma unroll
            for (int w = 1; w < 8; ++w) s += smem[g][w];
            v[g] = s;
        }
        float r  = sig_((v[0] + bih[j]) + (v[3] + bhh[j]));
        float z  = sig_((v[1] + bih[H + j]) + (v[4] + bhh[H + j]));
        float nn = tanhf((v[2] + bih[2 * H + j]) + r * (v[5] + bhh[2 * H + j]));
        float h  = (1.0f - z) * nn + z * hprev[j];
        hout[j] = h;
        hcopy[j] = h;
    }
}

// ---------------- energies + per-block (m,s) softmax partial ---------------
// 64 blocks x 1024 threads; warp per s-row (32 rows/block)
__global__ void k_energy(const float* __restrict__ enc, const float* __restrict__ h1) {
    __shared__ float se[32];
    int lane = threadIdx.x & 31, warp = threadIdx.x >> 5;
    int s = blockIdx.x * 32 + warp;
    const float4* w4 = reinterpret_cast<const float4*>(enc) + (size_t)s * 256;
    const float4* x4 = reinterpret_cast<const float4*>(h1);
    float e = 0.f;
#pragma unroll
    for (int i = lane; i < 256; i += 32) {
        float4 a = w4[i], c = x4[i];
        e += a.x * c.x + a.y * c.y + a.z * c.z + a.w * c.w;
    }
    e = wred(e);
    if (lane == 0) { g_energ[s] = e; se[warp] = e; }
    __syncthreads();
    if (warp == 0) {   // warp 0 merges the block's 32 energies
        float m = se[lane], sm = 1.0f;   // (m, s) for a single energy
#pragma unroll
        for (int o = 16; o; o >>= 1) {
            float m2 = __shfl_xor_sync(0xffffffffu, m, o);
            float s2 = __shfl_xor_sync(0xffffffffu, sm, o);
            msmerge(m, sm, m2, s2);
        }
        if (lane == 0) { g_am[blockIdx.x] = m; g_as[blockIdx.x] = sm; }
    }
}

// context partial: 32 blocks x 1024 threads; computes attn LSE locally
__global__ void k_ctx(const float* __restrict__ enc, float* __restrict__ attn_out) {
    __shared__ float sm[64], ss[64];
    int d = threadIdx.x;
    int s0 = blockIdx.x * 64;
    if (d < 64) { sm[d] = g_am[d]; ss[d] = g_as[d]; }
    __syncthreads();
#pragma unroll
    for (int off = 32; off >= 1; off >>= 1) {
        if (d < off) msmerge(sm[d], ss[d], sm[d + off], ss[d + off]);
        __syncthreads();
    }
    float lse = sm[0] + logf(ss[0]);
    if (d < 64) attn_out[s0 + d] = expf(g_energ[s0 + d] - lse);
    float acc = 0.f;
#pragma unroll 8
    for (int s = s0; s < s0 + 64; ++s)
        acc += expf(g_energ[s] - lse) * enc[(size_t)s * H + d];
    g_ctx_part[blockIdx.x * H + d] = acc;
}

// reduce 32 partials -> ctx; assemble xout = [h1, ctx]
__global__ void k_ctx_reduce(float* __restrict__ ctx_out) {
    int d = blockIdx.x * blockDim.x + threadIdx.x;
    float acc = 0.f;
#pragma unroll
    for (int c = 0; c < 32; ++c) acc += g_ctx_part[c * H + d];
    g_ctx[d] = acc;
    ctx_out[d] = acc;
    g_xout[d] = g_h1[d];
    g_xout[H + d] = acc;
}

// vocab GEMV: warp per row, full 2048 cols, bias fused
__global__ void k_vocab(const float* __restrict__ W, const float* __restrict__ b,
                        float* __restrict__ logits) {
    int v = (blockIdx.x * blockDim.x + threadIdx.x) >> 5;
    int lane = threadIdx.x & 31;
    if (v >= VOCAB) return;
    const float4* w4 = reinterpret_cast<const float4*>(W) + (size_t)v * 512;
    const float4* x4 = reinterpret_cast<const float4*>(g_xout);
    float s = 0.f;
#pragma unroll 8
    for (int i = lane; i < 512; i += 32) {
        float4 a = w4[i], c = x4[i];
        s += a.x * c.x + a.y * c.y + a.z * c.z + a.w * c.w;
    }
    s = wred(s);
    if (lane == 0) logits[v] = s + b[v];
}

// logit lse stage 1: 64 blocks x 256 threads, online (m,s) per block
__global__ void k_lse1(const float* __restrict__ logits) {
    __shared__ float sm[8], ss[8];
    const int CH = 786;
    int b = blockIdx.x;
    int lo = b * CH;
    int hi = min(lo + CH, VOCAB);
    int lane = threadIdx.x & 31, warp = threadIdx.x >> 5;
    float m = -INFINITY, s = 0.f;
    for (int v = lo + threadIdx.x; v < hi; v += 256) {
        float x = logits[v];
        if (x > m) { s = s * expf(m - x) + 1.0f; m = x; }
        else s += expf(x - m);
    }
#pragma unroll
    for (int o = 16; o; o >>= 1) {
        float m2 = __shfl_xor_sync(0xffffffffu, m, o);
        float s2 = __shfl_xor_sync(0xffffffffu, s, o);
        msmerge(m, s, m2, s2);
    }
    if (lane == 0) { sm[warp] = m; ss[warp] = s; }
    __syncthreads();
    if (threadIdx.x == 0) {
        float M = sm[0], Ssum = ss[0];
#pragma unroll
        for (int w = 1; w < 8; ++w) msmerge(M, Ssum, sm[w], ss[w]);
        g_lm[b] = M; g_ls[b] = Ssum;
    }
}

// finalize: each block recomputes the final LSE from 64 partials (L2-hot),
// then subtracts. Deterministic identical tree in every block.
__global__ void k_finalize(float* __restrict__ logits) {
    __shared__ float sm[64], ss[64];
    int t = threadIdx.x;
    if (t < 64) { sm[t] = g_lm[t]; ss[t] = g_ls[t]; }
    __syncthreads();
#pragma unroll
    for (int off = 32; off >= 1; off >>= 1) {
        if (t < off) msmerge(sm[t], ss[t], sm[t + off], ss[t + off]);
        __syncthreads();
    }
    float lse = sm[0] + logf(ss[0]);
    int v = blockIdx.x * blockDim.x + t;
    if (v < VOCAB) logits[v] -= lse;
}

// ---------------- launch ---------------------------------------------------

extern "C" void kernel_launch(void* const* d_in, const int* in_sizes, int n_in,
                              void* d_out, int out_size) {
    const int*   word     = (const int*)  d_in[0];
    const float* last_ctx = (const float*)d_in[1];
    const float* last_hid = (const float*)d_in[2];   // (2,1,H)
    const float* enc      = (const float*)d_in[3];   // (S,1,H)
    const float* emb      = (const float*)d_in[4];
    const float* W_ih0    = (const float*)d_in[5];
    const float* W_hh0    = (const float*)d_in[6];
    const float* b_ih0    = (const float*)d_in[7];
    const float* b_hh0    = (const float*)d_in[8];
    const float* W_ih1    = (const float*)d_in[9];
    const float* W_hh1    = (const float*)d_in[10];
    const float* b_ih1    = (const float*)d_in[11];
    const float* b_hh1    = (const float*)d_in[12];
    const float* W_out    = (const float*)d_in[13];
    const float* b_out    = (const float*)d_in[14];

    float* out       = (float*)d_out;
    float* out_logit = out;                  // [0, V)
    float* out_ctx   = out + VOCAB;          // context
    float* out_h0    = out + VOCAB + H;      // hidden[0]
    float* out_h1    = out + VOCAB + 2 * H;  // hidden[1]
    float* out_attn  = out + VOCAB + 3 * H;  // attn weights

    float *ph0, *ph1;
    cudaGetSymbolAddress((void**)&ph0, g_h0);
    cudaGetSymbolAddress((void**)&ph1, g_h1);

    // 1-2) fused GRU layers, block-per-output-element
    k_gru<2048, true><<<H, 256>>>(W_ih0, W_hh0, b_ih0, b_hh0, nullptr,
                                  emb, word, last_ctx, last_hid, ph0, out_h0);
    k_gru<1024, false><<<H, 256>>>(W_ih1, W_hh1, b_ih1, b_hh1, ph0,
                                   nullptr, nullptr, nullptr, last_hid + H, ph1, out_h1);

    // 3-5) attention (no single-warp kernels)
    k_energy<<<64, 1024>>>(enc, ph1);
    k_ctx<<<32, 1024>>>(enc, out_attn);
    k_ctx_reduce<<<4, 256>>>(out_ctx);

    // 6) vocab logits (bias fused)
    k_vocab<<<(VOCAB * 32 + 255) / 256, 256>>>(W_out, b_out, out_logit);

    // 7-8) log_softmax
    k_lse1<<<64, 256>>>(out_logit);
    k_finalize<<<(VOCAB + 255) / 256, 256>>>(out_logit);
}